// round 1
// baseline (speedup 1.0000x reference)
#include <cuda_runtime.h>
#include <math.h>

#define HEADS 12
#define HEAD_SIZE 64
#define HIDDEN 768
#define EPROJ (2 * HEADS * HEAD_SIZE) /* 1536 */
#define SEQ 1024
#define MAXB 8
#define NEGV 1000000000000.0f

// Scratch for rotated q/k, layout [B, H, N, 64] row-major.
__device__ float g_q[MAXB * HEADS * SEQ * HEAD_SIZE];
__device__ float g_k[MAXB * HEADS * SEQ * HEAD_SIZE];

// ---------------------------------------------------------------------------
// Kernel 1: proj = x @ W + b, then interleaved RoPE, scatter to g_q / g_k.
// Tiled fp32 GEMM: BM=64, BN=64, BK=16, 256 threads, 4x4 per-thread tile.
// ---------------------------------------------------------------------------
__global__ void proj_rope_kernel(const float* __restrict__ x,
                                 const float* __restrict__ Wm,
                                 const float* __restrict__ bias) {
    __shared__ __align__(16) float As[16][68];  // [k][m], pad 4 keeps 16B align
    __shared__ __align__(16) float Bs[16][68];  // [k][n]

    const int tid = threadIdx.x;
    const int tx = tid & 15;       // 0..15 -> cols
    const int ty = tid >> 4;       // 0..15 -> rows
    const int rowBase = blockIdx.y * 64;
    const int colBase = blockIdx.x * 64;

    float acc[4][4] = {};

    for (int k0 = 0; k0 < HIDDEN; k0 += 16) {
        // Load A tile 64x16 (transposed into As[k][m]); consecutive tid ->
        // consecutive k -> coalesced 64B global reads.
#pragma unroll
        for (int l = 0; l < 4; l++) {
            int idx = tid + l * 256;
            int ar = idx >> 4;
            int ak = idx & 15;
            As[ak][ar] = x[(size_t)(rowBase + ar) * HIDDEN + k0 + ak];
        }
        // Load B tile 16x64; consecutive tid -> consecutive cols -> coalesced.
#pragma unroll
        for (int l = 0; l < 4; l++) {
            int idx = tid + l * 256;
            int br = idx >> 6;
            int bc = idx & 63;
            Bs[br][bc] = Wm[(size_t)(k0 + br) * EPROJ + colBase + bc];
        }
        __syncthreads();

#pragma unroll
        for (int kk = 0; kk < 16; kk++) {
            float4 a4 = *(const float4*)&As[kk][ty * 4];
            float4 b4 = *(const float4*)&Bs[kk][tx * 4];
            float av[4] = {a4.x, a4.y, a4.z, a4.w};
            float bv[4] = {b4.x, b4.y, b4.z, b4.w};
#pragma unroll
            for (int i = 0; i < 4; i++)
#pragma unroll
                for (int j = 0; j < 4; j++) acc[i][j] += av[i] * bv[j];
        }
        __syncthreads();
    }

    // Epilogue: +bias, interleaved RoPE, scatter.
    // Thread's 4 cols are 4-aligned -> pairs (0,1),(2,3) are valid RoPE pairs
    // and stay within one head / one q-or-k half (64-aligned boundaries).
    const int cBase = colBase + tx * 4;
#pragma unroll
    for (int jp = 0; jp < 2; jp++) {
        const int c = cBase + jp * 2;
        const int h = c >> 7;
        const int inner = c & 127;
        const int half = inner >> 6;   // 0 = q, 1 = k
        const int d0 = inner & 63;     // even
        const float b0 = bias[c];
        const float b1 = bias[c + 1];
        // inv = 10000^(-d0/64); fp64 pow then round to fp32 to stay within
        // a couple ulp of the fp32 reference value.
        const float inv = (float)pow(10000.0, -(double)d0 / 64.0);
        float* dst = half ? g_k : g_q;
#pragma unroll
        for (int i = 0; i < 4; i++) {
            const int r = rowBase + ty * 4 + i;
            const int bb = r >> 10;
            const int n = r & (SEQ - 1);
            const float ang = (float)n * inv;
            float s, cs;
            sincosf(ang, &s, &cs);
            const float v0 = acc[i][jp * 2] + b0;
            const float v1 = acc[i][jp * 2 + 1] + b1;
            const float o0 = v0 * cs - v1 * s;
            const float o1 = v1 * cs + v0 * s;
            const size_t off =
                (((size_t)(bb * HEADS + h) * SEQ + n) * HEAD_SIZE) + d0;
            dst[off] = o0;
            dst[off + 1] = o1;
        }
    }
}

// ---------------------------------------------------------------------------
// Kernel 2: per (b,h) logits tile:
//   v = sum_d q[m,d]*k[n,d]
//   v = v*mq + NEG*(mq-1); v = v*mk + NEG*(mk-1); if (m>n) v -= NEG; v *= 0.125
// BM=BN=64, full K=64 resident, 256 threads, 4x4 per thread.
// ---------------------------------------------------------------------------
__global__ void logits_kernel(const float* __restrict__ mask,
                              float* __restrict__ out) {
    __shared__ __align__(16) float Qs[64][68];  // [d][m]
    __shared__ __align__(16) float Ks[64][68];  // [d][n]

    const int tid = threadIdx.x;
    const int tx = tid & 15;
    const int ty = tid >> 4;
    const int z = blockIdx.z;           // b*HEADS + h
    const int b = z / HEADS;
    const int m0 = blockIdx.y * 64;
    const int n0 = blockIdx.x * 64;

    const float* qb = g_q + (size_t)z * SEQ * HEAD_SIZE;
    const float* kb = g_k + (size_t)z * SEQ * HEAD_SIZE;

    // Load 64x64 tiles (transpose into [d][row]); float4 global reads.
#pragma unroll
    for (int it = 0; it < 4; it++) {
        int e = tid + it * 256;        // float4 index, 16 per row
        int row = e >> 4;
        int dd = (e & 15) * 4;
        float4 v = *(const float4*)&qb[(size_t)(m0 + row) * HEAD_SIZE + dd];
        Qs[dd + 0][row] = v.x; Qs[dd + 1][row] = v.y;
        Qs[dd + 2][row] = v.z; Qs[dd + 3][row] = v.w;
        float4 w = *(const float4*)&kb[(size_t)(n0 + row) * HEAD_SIZE + dd];
        Ks[dd + 0][row] = w.x; Ks[dd + 1][row] = w.y;
        Ks[dd + 2][row] = w.z; Ks[dd + 3][row] = w.w;
    }
    __syncthreads();

    float acc[4][4] = {};
#pragma unroll
    for (int d = 0; d < 64; d++) {
        float4 a4 = *(const float4*)&Qs[d][ty * 4];
        float4 b4 = *(const float4*)&Ks[d][tx * 4];
        float av[4] = {a4.x, a4.y, a4.z, a4.w};
        float bv[4] = {b4.x, b4.y, b4.z, b4.w};
#pragma unroll
        for (int i = 0; i < 4; i++)
#pragma unroll
            for (int j = 0; j < 4; j++) acc[i][j] += av[i] * bv[j];
    }

    float mqv[4], mkv[4];
#pragma unroll
    for (int i = 0; i < 4; i++) mqv[i] = mask[(size_t)b * SEQ + m0 + ty * 4 + i];
#pragma unroll
    for (int j = 0; j < 4; j++) mkv[j] = mask[(size_t)b * SEQ + n0 + tx * 4 + j];

#pragma unroll
    for (int i = 0; i < 4; i++) {
        const int m = m0 + ty * 4 + i;
        float4 o;
        float vv[4];
#pragma unroll
        for (int j = 0; j < 4; j++) {
            const int n = n0 + tx * 4 + j;
            float v = acc[i][j];
            v = v * mqv[i] + NEGV * (mqv[i] - 1.0f);
            v = v * mkv[j] + NEGV * (mkv[j] - 1.0f);
            if (m > n) v -= NEGV;
            vv[j] = v * 0.125f;
        }
        o.x = vv[0]; o.y = vv[1]; o.z = vv[2]; o.w = vv[3];
        *(float4*)&out[(((size_t)z * SEQ + m) * SEQ) + n0 + tx * 4] = o;
    }
}

extern "C" void kernel_launch(void* const* d_in, const int* in_sizes, int n_in,
                              void* d_out, int out_size) {
    const float* x = (const float*)d_in[0];
    const float* W = (const float*)d_in[1];
    const float* b = (const float*)d_in[2];
    const float* mask = (const float*)d_in[3];
    float* out = (float*)d_out;

    const int M = in_sizes[0] / HIDDEN;   // B * SEQ = 8192
    const int B = M / SEQ;                // 8

    dim3 g1(EPROJ / 64, M / 64);
    proj_rope_kernel<<<g1, 256>>>(x, W, b);

    dim3 g2(SEQ / 64, SEQ / 64, B * HEADS);
    logits_kernel<<<g2, 256>>>(mask, out);
}

// round 3
// speedup vs baseline: 5.1567x; 5.1567x over previous
#include <cuda_runtime.h>
#include <cuda_bf16.h>
#include <stdint.h>
#include <math.h>

#define HEADS 12
#define HEAD_SIZE 64
#define HIDDEN 768
#define EPROJ 1536
#define SEQ 1024
#define NB 8
#define NEGV 1000000000000.0f

// bf16 staging buffers
__device__ __align__(128) __nv_bfloat16 g_xb[NB * SEQ * HIDDEN];   // [8192][768]
__device__ __align__(128) __nv_bfloat16 g_wt[EPROJ * HIDDEN];      // [1536][768] = W^T
__device__ __align__(128) __nv_bfloat16 g_q[NB * HEADS * SEQ * HEAD_SIZE];
__device__ __align__(128) __nv_bfloat16 g_k[NB * HEADS * SEQ * HEAD_SIZE];

#define SWZ(o) ((o) ^ (((o) >> 3) & 0x70))

__device__ __forceinline__ uint32_t smem_u32(const void* p) {
    uint32_t a;
    asm("{ .reg .u64 t; cvta.to.shared.u64 t, %1; cvt.u32.u64 %0, t; }"
        : "=r"(a) : "l"(p));
    return a;
}

__device__ __forceinline__ void ldmx4(uint32_t* r, uint32_t addr) {
    asm volatile("ldmatrix.sync.aligned.m8n8.x4.shared.b16 {%0,%1,%2,%3}, [%4];"
                 : "=r"(r[0]), "=r"(r[1]), "=r"(r[2]), "=r"(r[3]) : "r"(addr));
}
__device__ __forceinline__ void ldmx2(uint32_t* r, uint32_t addr) {
    asm volatile("ldmatrix.sync.aligned.m8n8.x2.shared.b16 {%0,%1}, [%2];"
                 : "=r"(r[0]), "=r"(r[1]) : "r"(addr));
}
__device__ __forceinline__ void mma16816(float* c, const uint32_t* a,
                                         const uint32_t* b) {
    asm volatile(
        "mma.sync.aligned.m16n8k16.row.col.f32.bf16.bf16.f32 "
        "{%0,%1,%2,%3}, {%4,%5,%6,%7}, {%8,%9}, {%0,%1,%2,%3};"
        : "+f"(c[0]), "+f"(c[1]), "+f"(c[2]), "+f"(c[3])
        : "r"(a[0]), "r"(a[1]), "r"(a[2]), "r"(a[3]), "r"(b[0]), "r"(b[1]));
}

// ---------------------------------------------------------------------------
// conversion kernels
// ---------------------------------------------------------------------------
__global__ void conv_x_kernel(const float* __restrict__ x) {
    int i = blockIdx.x * blockDim.x + threadIdx.x;  // float4 index
    float4 v = ((const float4*)x)[i];
    __nv_bfloat162 lo, hi;
    lo.x = __float2bfloat16(v.x); lo.y = __float2bfloat16(v.y);
    hi.x = __float2bfloat16(v.z); hi.y = __float2bfloat16(v.w);
    uint2 u;
    u.x = *(uint32_t*)&lo; u.y = *(uint32_t*)&hi;
    ((uint2*)g_xb)[i] = u;
}

__global__ void conv_wt_kernel(const float* __restrict__ W) {
    __shared__ float t[32][33];
    int bx = blockIdx.x * 32, by = blockIdx.y * 32;
#pragma unroll
    for (int j = 0; j < 4; j++)
        t[threadIdx.y + j * 8][threadIdx.x] =
            W[(size_t)(by + threadIdx.y + j * 8) * EPROJ + bx + threadIdx.x];
    __syncthreads();
#pragma unroll
    for (int j = 0; j < 4; j++)
        g_wt[(size_t)(bx + threadIdx.y + j * 8) * HIDDEN + by + threadIdx.x] =
            __float2bfloat16(t[threadIdx.x][threadIdx.y + j * 8]);
}

// ---------------------------------------------------------------------------
// Kernel 1: proj = x @ W (+bias) then RoPE -> g_q / g_k (bf16)
// CTA tile 128x128, K staged in chunks of 64. 8 warps: 2(m) x 4(n), warp
// tile 64x32. mma.sync m16n8k16 bf16.
// ---------------------------------------------------------------------------
__global__ void proj_kernel(const float* __restrict__ bias) {
    __shared__ __align__(128) __nv_bfloat16 sA[128 * 64];  // [m][k] 128B rows
    __shared__ __align__(128) __nv_bfloat16 sB[128 * 64];  // [n][k]
    __shared__ float s_inv[32];
    __shared__ float s_bias[128];

    const int tid = threadIdx.x;
    const int lane = tid & 31;
    const int wid = tid >> 5;
    const int wm = wid & 1;   // 0..1
    const int wn = wid >> 1;  // 0..3
    const int h = blockIdx.x;             // head tile (12)
    const int rowBase = blockIdx.y * 128; // token rows
    const int colBase = h * 128;

    if (tid < 32) s_inv[tid] = exp2f(-(float)(2 * tid) * (13.287712379549449f / 64.0f));
    if (tid < 128) s_bias[tid] = bias[colBase + tid];

    const uint32_t sAb = smem_u32(sA);
    const uint32_t sBb = smem_u32(sB);

    float acc[4][4][4] = {};

    for (int ch = 0; ch < 12; ch++) {
        const int k0 = ch * 64;
        __syncthreads();
#pragma unroll
        for (int i = 0; i < 4; i++) {
            int e = tid + i * 256;   // uint4 index, 1024 per tile
            int r = e >> 3;
            int c = e & 7;
            uint32_t so = SWZ((uint32_t)(r * 128 + c * 16));
            *(uint4*)((char*)sA + so) =
                *(const uint4*)(g_xb + (size_t)(rowBase + r) * HIDDEN + k0 + c * 8);
            *(uint4*)((char*)sB + so) =
                *(const uint4*)(g_wt + (size_t)(colBase + r) * HIDDEN + k0 + c * 8);
        }
        __syncthreads();

#pragma unroll
        for (int ks = 0; ks < 4; ks++) {
            uint32_t aF[4][4], bF[4][2];
#pragma unroll
            for (int mi = 0; mi < 4; mi++) {
                int r = wm * 64 + mi * 16 + (lane & 15);
                int cc = ks * 2 + (lane >> 4);
                ldmx4(aF[mi], sAb + SWZ((uint32_t)(r * 128 + cc * 16)));
            }
#pragma unroll
            for (int ni = 0; ni < 4; ni++) {
                int l = lane & 15;
                int r = wn * 32 + ni * 8 + (l & 7);
                int cc = ks * 2 + (l >> 3);
                ldmx2(bF[ni], sBb + SWZ((uint32_t)(r * 128 + cc * 16)));
            }
#pragma unroll
            for (int mi = 0; mi < 4; mi++)
#pragma unroll
                for (int ni = 0; ni < 4; ni++)
                    mma16816(acc[mi][ni], aF[mi], bF[ni]);
        }
    }

    // Epilogue: bias + interleaved RoPE, write bf16 to g_q / g_k.
    // C frag: c0,c1 at (row=lane>>2, col=(lane&3)*2 (+1)); c2,c3 at row+8.
    const int colW = wn * 32;             // warp col base within 128
    const int half = colW >> 6;           // 0=q, 1=k (warp tile within one half)
    __nv_bfloat16* dstBase = half ? g_k : g_q;
#pragma unroll
    for (int mi = 0; mi < 4; mi++) {
#pragma unroll
        for (int rr = 0; rr < 2; rr++) {
            const int r = rowBase + wm * 64 + mi * 16 + (lane >> 2) + rr * 8;
            const int bb = r >> 10;
            const int n = r & (SEQ - 1);
            const float fn = (float)n;
            __nv_bfloat16* drow =
                dstBase + ((size_t)(bb * HEADS + h) * SEQ + n) * HEAD_SIZE;
#pragma unroll
            for (int ni = 0; ni < 4; ni++) {
                const int col = colW + ni * 8 + (lane & 3) * 2;  // within 128
                const int d0 = col & 63;
                float s, cs;
                sincosf(fn * s_inv[d0 >> 1], &s, &cs);
                const float v0 = acc[mi][ni][rr * 2 + 0] + s_bias[col];
                const float v1 = acc[mi][ni][rr * 2 + 1] + s_bias[col + 1];
                __nv_bfloat162 o;
                o.x = __float2bfloat16(v0 * cs - v1 * s);
                o.y = __float2bfloat16(v1 * cs + v0 * s);
                *(__nv_bfloat162*)(drow + d0) = o;
            }
        }
    }
}

// ---------------------------------------------------------------------------
// Kernel 2: logits tile 128x128 per CTA: D = q @ k^T, mask/causal/scale.
// ---------------------------------------------------------------------------
__global__ void logits_kernel(const float* __restrict__ mask,
                              float* __restrict__ out) {
    __shared__ __align__(128) __nv_bfloat16 sQ[128 * 64];
    __shared__ __align__(128) __nv_bfloat16 sK[128 * 64];
    __shared__ float s_mk[128];

    const int tid = threadIdx.x;
    const int lane = tid & 31;
    const int wid = tid >> 5;
    const int wm = wid & 1;
    const int wn = wid >> 1;
    const int z = blockIdx.z;
    const int b = z / HEADS;
    const int m0 = blockIdx.y << 7;
    const int n0 = blockIdx.x << 7;

    const __nv_bfloat16* qsrc = g_q + ((size_t)z * SEQ + m0) * HEAD_SIZE;
    const __nv_bfloat16* ksrc = g_k + ((size_t)z * SEQ + n0) * HEAD_SIZE;

#pragma unroll
    for (int i = 0; i < 4; i++) {
        int e = tid + i * 256;
        uint32_t so = SWZ((uint32_t)(e * 16));
        *(uint4*)((char*)sQ + so) = ((const uint4*)qsrc)[e];
        *(uint4*)((char*)sK + so) = ((const uint4*)ksrc)[e];
    }
    if (tid < 128) s_mk[tid] = mask[(size_t)b * SEQ + n0 + tid];
    __syncthreads();

    const uint32_t sQb = smem_u32(sQ);
    const uint32_t sKb = smem_u32(sK);

    float acc[4][4][4] = {};
#pragma unroll
    for (int ks = 0; ks < 4; ks++) {
        uint32_t aF[4][4], bF[4][2];
#pragma unroll
        for (int mi = 0; mi < 4; mi++) {
            int r = wm * 64 + mi * 16 + (lane & 15);
            int cc = ks * 2 + (lane >> 4);
            ldmx4(aF[mi], sQb + SWZ((uint32_t)(r * 128 + cc * 16)));
        }
#pragma unroll
        for (int ni = 0; ni < 4; ni++) {
            int l = lane & 15;
            int r = wn * 32 + ni * 8 + (l & 7);
            int cc = ks * 2 + (l >> 3);
            ldmx2(bF[ni], sKb + SWZ((uint32_t)(r * 128 + cc * 16)));
        }
#pragma unroll
        for (int mi = 0; mi < 4; mi++)
#pragma unroll
            for (int ni = 0; ni < 4; ni++)
                mma16816(acc[mi][ni], aF[mi], bF[ni]);
    }

    // Epilogue: mask, causal, scale; float2 stores.
#pragma unroll
    for (int mi = 0; mi < 4; mi++) {
#pragma unroll
        for (int rr = 0; rr < 2; rr++) {
            const int m = m0 + wm * 64 + mi * 16 + (lane >> 2) + rr * 8;
            const float mq = mask[(size_t)b * SEQ + m];
            const float rbias = NEGV * (mq - 1.0f);
            float* orow = out + ((size_t)z * SEQ + m) * SEQ;
#pragma unroll
            for (int ni = 0; ni < 4; ni++) {
                const int col = wn * 32 + ni * 8 + (lane & 3) * 2;
                const int nn = n0 + col;
                float2 o;
#pragma unroll
                for (int q = 0; q < 2; q++) {
                    const float mk = s_mk[col + q];
                    float v = acc[mi][ni][rr * 2 + q];
                    v = v * mq + rbias;
                    v = v * mk + NEGV * (mk - 1.0f);
                    if (m > nn + q) v -= NEGV;
                    (&o.x)[q] = v * 0.125f;
                }
                *(float2*)(orow + nn) = o;
            }
        }
    }
}

// ---------------------------------------------------------------------------
extern "C" void kernel_launch(void* const* d_in, const int* in_sizes, int n_in,
                              void* d_out, int out_size) {
    const float* x = (const float*)d_in[0];
    const float* W = (const float*)d_in[1];
    const float* bias = (const float*)d_in[2];
    const float* mask = (const float*)d_in[3];
    float* out = (float*)d_out;

    conv_x_kernel<<<(NB * SEQ * HIDDEN / 4) / 256, 256>>>(x);
    conv_wt_kernel<<<dim3(EPROJ / 32, HIDDEN / 32), dim3(32, 8)>>>(W);

    proj_kernel<<<dim3(EPROJ / 128, NB * SEQ / 128), 256>>>(bias);

    logits_kernel<<<dim3(SEQ / 128, SEQ / 128, NB * HEADS), 256>>>(mask, out);
}